// round 17
// baseline (speedup 1.0000x reference)
#include <cuda_runtime.h>
#include <cuda_fp16.h>
#include <math.h>
#include <stdint.h>

// HashEmbedder: 16-level 2D multires hash grid, 2 feats/level, T=2^19.
// Phase 1: build fp16 cell-packed corner table (16B per cell).
// Phase 2: TILE-LOCAL SPATIAL SORT. Each block owns 2048 consecutive points,
// counting-sorts them by 16x16 spatial bin in SMEM, then processes in sorted
// order (4 thr/point). Warp's 8 points land in ~1 bin -> coarse-level gathers
// collapse onto shared 128B lines. Stores scatter only within the tile's
// 256KB output window (full lines, L2-absorbed) -- avoids R8's global-
// permutation DRAM disaster.

#define NLEV 16
#define TLOG2 19
#define TSIZE (1u << TLOG2)
#define HMASK ((1u << TLOG2) - 1u)
#define PRIME1 2654435761u

#define TILE 2048

// Sum of res^2 over the 16 levels = 706,816 cells; margin for safety.
#define MAX_CELLS 710000
__device__ uint4 g_packed[MAX_CELLS];   // 16B per cell: h00,h10,h01,h11

struct Params {
    float resF[NLEV];
    int   resI[NLEV];
    int   off[NLEV];
    int   total;
};

// ---------------------------------------------------------------------------
// Phase 1: build packed table. One thread per cell.
// ---------------------------------------------------------------------------
__global__ __launch_bounds__(256) void build_packed_kernel(
    const float* __restrict__ emb, Params pm, int total_cells)
{
    int i = blockIdx.x * blockDim.x + threadIdx.x;
    if (i >= total_cells) return;

    int l = 0;
#pragma unroll
    for (int k = 1; k < NLEV; ++k) l += (i >= pm.off[k]);

    int c   = i - pm.off[l];
    int res = pm.resI[l];
    int cy  = c / res;
    int cx  = c - cy * res;

    uint32_t ux0 = (uint32_t)cx;
    uint32_t ux1 = (uint32_t)(cx + 1);
    uint32_t yp0 = (uint32_t)cy * PRIME1;
    uint32_t yp1 = (uint32_t)(cy + 1) * PRIME1;

    uint32_t a00 = (ux0 ^ yp0) & HMASK;
    uint32_t a10 = (ux1 ^ yp0) & HMASK;
    uint32_t a01 = (ux0 ^ yp1) & HMASK;
    uint32_t a11 = (ux1 ^ yp1) & HMASK;

    const float2* __restrict__ tab =
        ((const float2*)emb) + ((size_t)l << TLOG2);

    float2 f00 = __ldg(tab + a00);
    float2 f10 = __ldg(tab + a10);
    float2 f01 = __ldg(tab + a01);
    float2 f11 = __ldg(tab + a11);

    half2 h00 = __float22half2_rn(f00);
    half2 h10 = __float22half2_rn(f10);
    half2 h01 = __float22half2_rn(f01);
    half2 h11 = __float22half2_rn(f11);

    uint4 r;
    r.x = *(const uint32_t*)&h00;
    r.y = *(const uint32_t*)&h10;
    r.z = *(const uint32_t*)&h01;
    r.w = *(const uint32_t*)&h11;
    g_packed[i] = r;
}

// ---------------------------------------------------------------------------
// Phase 2: tile-local sort + gather. Block = 256 threads, tile = 2048 points.
// ---------------------------------------------------------------------------
__global__ __launch_bounds__(256) void hash_embed_kernel(
    const float* __restrict__ x,
    float* __restrict__ out,
    int n_points,
    Params pm)
{
    __shared__ float2         s_xy[TILE];     // 16 KB
    __shared__ unsigned short s_ord[TILE];    // 4 KB
    __shared__ int            s_hist[256];    // 1 KB (bases/cursors)
    __shared__ int            s_scan[256];    // 1 KB
    __shared__ float4         s_lv[NLEV];

    int tid = threadIdx.x;

    if (tid < NLEV) {
        s_lv[tid] = make_float4(
            pm.resF[tid],
            __int_as_float(pm.resI[tid]),
            __int_as_float(pm.off[tid]),
            0.0f);
    }
    s_hist[tid] = 0;
    __syncthreads();

    int tile_base = blockIdx.x * TILE;
    int tile_n    = min(TILE, n_points - tile_base);

    // --- Phase A: load xy, compute 16x16 spatial bin, histogram ---
    unsigned char key[8];
#pragma unroll
    for (int k = 0; k < 8; ++k) {
        int i = (k << 8) + tid;
        if (i < tile_n) {
            float2 xy = __ldg(((const float2*)x) + tile_base + i);
            s_xy[i] = xy;
            int bx = min(15, max(0, (int)(xy.x * 16.0f)));
            int by = min(15, max(0, (int)(xy.y * 16.0f)));
            key[k] = (unsigned char)((by << 4) | bx);
            atomicAdd(&s_hist[key[k]], 1);
        }
    }
    __syncthreads();

    // --- Phase B: exclusive scan over 256 bins (Hillis-Steele) ---
    int v = s_hist[tid];
    s_scan[tid] = v;
    __syncthreads();
#pragma unroll
    for (int d = 1; d < 256; d <<= 1) {
        int t2 = (tid >= d) ? s_scan[tid - d] : 0;
        __syncthreads();
        s_scan[tid] += t2;
        __syncthreads();
    }
    s_hist[tid] = s_scan[tid] - v;   // exclusive base -> cursor
    __syncthreads();

    // --- Phase C: scatter point indices into bin order ---
#pragma unroll
    for (int k = 0; k < 8; ++k) {
        int i = (k << 8) + tid;
        if (i < tile_n) {
            int pos = atomicAdd(&s_hist[key[k]], 1);
            s_ord[pos] = (unsigned short)i;
        }
    }
    __syncthreads();

    // --- Phase D: gather + lerp in sorted order; 4 threads per point ---
    int lb = (tid & 3) << 2;       // base level per thread: 0,4,8,12

    float resF[4];
    int   ri[4], off[4];
#pragma unroll
    for (int j = 0; j < 4; ++j) {
        float4 lv = s_lv[lb + j];
        resF[j] = lv.x;
        ri[j]   = __float_as_int(lv.y);
        off[j]  = __float_as_int(lv.z);
    }

    for (int s = tid >> 2; s < tile_n; s += 64) {
        int    i  = s_ord[s];          // 4 threads broadcast
        float2 xy = s_xy[i];

        int   idx[4];
        float wx[4], wy[4];
#pragma unroll
        for (int j = 0; j < 4; ++j) {
            float px = xy.x * resF[j];
            float py = xy.y * resF[j];
            float fx = floorf(px);
            float fy = floorf(py);
            wx[j] = px - fx;
            wy[j] = py - fy;

            int ix = min(max((int)fx, 0), ri[j] - 1);
            int iy = min(max((int)fy, 0), ri[j] - 1);
            idx[j] = off[j] + iy * ri[j] + ix;
        }

        uint4 rr[4];
#pragma unroll
        for (int j = 0; j < 4; ++j) {
            if (lb + j < 7) {
                rr[j] = __ldg(&g_packed[idx[j]]);    // L1-resident coarse
            } else {
                uint4 t;
                asm("ld.global.cg.v4.u32 {%0,%1,%2,%3}, [%4];"
                    : "=r"(t.x), "=r"(t.y), "=r"(t.z), "=r"(t.w)
                    : "l"(&g_packed[idx[j]]));       // L2-only fine
                rr[j] = t;
            }
        }

        float o[8];
#pragma unroll
        for (int j = 0; j < 4; ++j) {
            float2 f00 = __half22float2(*(const half2*)&rr[j].x);
            float2 f10 = __half22float2(*(const half2*)&rr[j].y);
            float2 f01 = __half22float2(*(const half2*)&rr[j].z);
            float2 f11 = __half22float2(*(const half2*)&rr[j].w);

            float u = 1.0f - wx[j];
            float w = 1.0f - wy[j];

            o[2 * j]     = (f00.x * u + f10.x * wx[j]) * w + (f01.x * u + f11.x * wx[j]) * wy[j];
            o[2 * j + 1] = (f00.y * u + f10.y * wx[j]) * w + (f01.y * u + f11.y * wx[j]) * wy[j];
        }

        // Full 128B line per point; scatter stays within the tile's 256KB
        // output window. Streaming (evict-first) stores.
        float* dst = out + (size_t)(tile_base + i) * (NLEV * 2) + lb * 2;
        asm volatile("st.global.cs.v4.f32 [%0], {%1,%2,%3,%4};"
                     :: "l"(dst), "f"(o[0]), "f"(o[1]), "f"(o[2]), "f"(o[3]));
        asm volatile("st.global.cs.v4.f32 [%0], {%1,%2,%3,%4};"
                     :: "l"(dst + 4), "f"(o[4]), "f"(o[5]), "f"(o[6]), "f"(o[7]));
    }
}

extern "C" void kernel_launch(void* const* d_in, const int* in_sizes, int n_in,
                              void* d_out, int out_size)
{
    const float* x   = (const float*)d_in[0];
    const float* emb = (const float*)d_in[1];
    float* out       = (float*)d_out;

    int n_points = in_sizes[0] / 2;

    Params pm;
    double b = exp((log(512.0) - log(16.0)) / 15.0);
    int acc = 0;
    for (int l = 0; l < NLEV; ++l) {
        double r = floor(16.0 * pow(b, (double)l));
        pm.resF[l] = (float)r;
        pm.resI[l] = (int)r;
        pm.off[l]  = acc;
        acc += pm.resI[l] * pm.resI[l];
    }
    pm.total = acc;

    static bool configured = false;
    if (!configured) {
        cudaFuncSetAttribute(hash_embed_kernel,
                             cudaFuncAttributePreferredSharedMemoryCarveout,
                             cudaSharedmemCarveoutMaxL1);
        configured = true;
    }

    // Phase 1: build packed corner table (fp16, 16B per cell)
    {
        int threads = 256;
        int blocks = (acc + threads - 1) / threads;
        build_packed_kernel<<<blocks, threads>>>(emb, pm, acc);
    }

    // Phase 2: tile-sorted gather + lerp
    {
        int blocks = (n_points + TILE - 1) / TILE;
        hash_embed_kernel<<<blocks, 256>>>(x, out, n_points, pm);
    }
}